// round 9
// baseline (speedup 1.0000x reference)
#include <cuda_runtime.h>
#include <math.h>

#define B_   32
#define T_   512
#define IND  512
#define U_   1024
#define G4   4096   // 4*U
#define NBLK 128
#define NTHR 512

// ---------------- scratch (static device globals; no allocs allowed) ----------
__device__ __align__(16) float g_xproj[(size_t)B_ * T_ * G4];  // 256 MB [b*T+t][4U]
__device__ __align__(16) float g_h[2][U_ * B_];                // ping-pong hT: [u][b]
__device__ unsigned g_count;   // monotonic arrival counter (reset by init_state)

// ---------------- init: zero h0 + reset barrier every launch ------------------
__global__ void init_state() {
    int i = blockIdx.x * blockDim.x + threadIdx.x;
    if (i < U_ * B_) g_h[0][i] = 0.f;
    if (i == 0) g_count = 0u;
}

#define FMA2(acc, a, b) \
    asm("fma.rn.f32x2 %0, %1, %2, %0;" : "+l"(acc) : "l"(a), "l"(b))
#define DUP32(dst, src) \
    asm("mov.b64 %0, {%1, %1};" : "=l"(dst) : "r"(src))
#define UNPK(lo, hi, v) \
    asm("mov.b64 {%0, %1}, %2;" : "=r"(lo), "=r"(hi) : "l"(v))

// ---------------- Kernel 1: x_proj = data @ Wx + b (FFMA2 mainloop) -----------
__global__ __launch_bounds__(256) void gemm_xproj(
    const float* __restrict__ A, const float* __restrict__ Bw,
    const float* __restrict__ bias)
{
    const int K = IND, N = G4;
    __shared__ float As[16][132];
    __shared__ float Bs[16][128];

    int tid = threadIdx.x;
    int bm = blockIdx.y * 128;
    int bn = blockIdx.x * 128;

    int ty = tid >> 4;
    int tx = tid & 15;

    int arow = tid >> 2;
    int acol = (tid & 3) * 4;
    int brow = tid >> 5;
    int bcol = (tid & 31) * 4;

    const float* Aptr = A + (size_t)(bm + arow) * K + acol;
    const float* Bptr = Bw + (size_t)brow * N + bn + bcol;

    unsigned long long acc2[8][4];
    #pragma unroll
    for (int i = 0; i < 8; i++)
        #pragma unroll
        for (int j = 0; j < 4; j++) acc2[i][j] = 0ULL;

    for (int k0 = 0; k0 < K; k0 += 16) {
        float4 a0 = *(const float4*)(Aptr);
        float4 a1 = *(const float4*)(Aptr + (size_t)64 * K);
        float4 b0 = *(const float4*)(Bptr);
        float4 b1 = *(const float4*)(Bptr + (size_t)8 * N);

        As[acol + 0][arow] = a0.x; As[acol + 1][arow] = a0.y;
        As[acol + 2][arow] = a0.z; As[acol + 3][arow] = a0.w;
        As[acol + 0][arow + 64] = a1.x; As[acol + 1][arow + 64] = a1.y;
        As[acol + 2][arow + 64] = a1.z; As[acol + 3][arow + 64] = a1.w;
        *(float4*)&Bs[brow][bcol]     = b0;
        *(float4*)&Bs[brow + 8][bcol] = b1;
        __syncthreads();

        #pragma unroll
        for (int kk = 0; kk < 16; kk++) {
            float a[8];
            *(float4*)&a[0] = *(const float4*)&As[kk][ty * 8];
            *(float4*)&a[4] = *(const float4*)&As[kk][ty * 8 + 4];
            ulonglong2 bA = *(const ulonglong2*)&Bs[kk][tx * 8];
            ulonglong2 bB = *(const ulonglong2*)&Bs[kk][tx * 8 + 4];
            #pragma unroll
            for (int i = 0; i < 8; i++) {
                unsigned long long ad;
                DUP32(ad, __float_as_uint(a[i]));
                FMA2(acc2[i][0], ad, bA.x);
                FMA2(acc2[i][1], ad, bA.y);
                FMA2(acc2[i][2], ad, bB.x);
                FMA2(acc2[i][3], ad, bB.y);
            }
        }
        __syncthreads();
        Aptr += 16;
        Bptr += (size_t)16 * N;
    }

    float bv[8];
    #pragma unroll
    for (int j = 0; j < 8; j++) bv[j] = bias[bn + tx * 8 + j];

    #pragma unroll
    for (int i = 0; i < 8; i++) {
        float c[8];
        #pragma unroll
        for (int j = 0; j < 4; j++) {
            unsigned lo, hi;
            UNPK(lo, hi, acc2[i][j]);
            c[2 * j]     = __uint_as_float(lo) + bv[2 * j];
            c[2 * j + 1] = __uint_as_float(hi) + bv[2 * j + 1];
        }
        float* crow = g_xproj + (size_t)(bm + ty * 8 + i) * N + bn + tx * 8;
        *(float4*)crow       = make_float4(c[0], c[1], c[2], c[3]);
        *(float4*)(crow + 4) = make_float4(c[4], c[5], c[6], c[7]);
    }
}

// ---------------- Kernel 2: persistent LSTM recurrence ------------------------
__device__ __forceinline__ float sigmoidf_(float x) {
    return 1.f / (1.f + __expf(-x));
}
__device__ __forceinline__ float tanhf_(float x) {
    return 2.f / (1.f + __expf(-2.f * x)) - 1.f;
}

extern __shared__ float smem_dyn[];

// 128 blocks x 512 threads (1/SM, all resident). Block owns 8 units x 4 gates
// = 32 Wh columns pinned in smem (128 KB). Warp w (0..15) reduces K-chunk
// [w*64,+64). Explicit 2-stage h prefetch (depth 4 k). Monotonic-count grid
// barrier; next-step x_proj prefetched into the barrier wait.
__global__ __launch_bounds__(NTHR) void lstm_persistent(
    const float* __restrict__ Wh,   // [1024][4096]
    float* __restrict__ out)        // [32][512][1024]
{
    float* ws   = smem_dyn;                  // [1024][32]  128 KB
    float* part = smem_dyn + U_ * 32;        // [16*4*8][36] 72 KB

    const int tid  = threadIdx.x;
    const int w    = tid >> 5;               // 0..15
    const int lane = tid & 31;
    const int g    = lane & 3;
    const int tb   = lane >> 2;
    const int u0   = blockIdx.x * 8;

    // ---- load this block's Wh slice into smem (once) ----
    for (int idx = tid; idx < U_ * 8; idx += NTHR) {   // float4 granules
        int k  = idx >> 3;
        int r  = idx & 7;
        int g2 = r >> 1;
        int hf = r & 1;
        float4 v = *(const float4*)(Wh + (size_t)k * G4 + g2 * U_ + u0 + hf * 4);
        *(float4*)&ws[k * 32 + g2 * 8 + hf * 4] = v;
    }

    const int eb = (tid >> 3) & 31;          // epilogue batch (tid<256 active)
    const int eu = tid & 7;                  // epilogue unit
    float c_reg = 0.f;

    // prefetch x_proj for t=0
    const float* xpb = g_xproj + (size_t)eb * T_ * G4 + u0 + eu;
    float xpv0 = 0.f, xpv1 = 0.f, xpv2 = 0.f, xpv3 = 0.f;
    if (tid < 256) {
        xpv0 = __ldg(xpb);
        xpv1 = __ldg(xpb + U_);
        xpv2 = __ldg(xpb + 2 * U_);
        xpv3 = __ldg(xpb + 3 * U_);
    }
    __syncthreads();

    const float* wsp_base = ws + (size_t)(w * 64) * 32 + g * 8;

    for (int t = 0; t < T_; t++) {
        const float* __restrict__ h_in = g_h[t & 1];
        float* __restrict__ h_out      = g_h[(t + 1) & 1];

        unsigned long long acc2[4][4];   // [unit-pair][batch]
        #pragma unroll
        for (int i = 0; i < 4; i++)
            #pragma unroll
            for (int j = 0; j < 4; j++) acc2[i][j] = 0ULL;

        const float* wsp = wsp_base;
        const float4* hp = (const float4*)(h_in + (w * 64) * B_) + tb;

        // 2-stage software pipeline, 4-k groups
        float4 hbuf[4];
        #pragma unroll
        for (int i = 0; i < 4; i++) hbuf[i] = __ldcg(hp + i * 8);

        #pragma unroll 2
        for (int kg = 0; kg < 16; kg++) {          // 16 groups of 4 k
            float4 hnext[4];
            if (kg < 15) {
                #pragma unroll
                for (int i = 0; i < 4; i++)
                    hnext[i] = __ldcg(hp + (kg + 1) * 32 + i * 8);
            }
            #pragma unroll
            for (int kk = 0; kk < 4; kk++) {
                ulonglong2 wA = *(const ulonglong2*)(wsp + kk * 32);
                ulonglong2 wB = *(const ulonglong2*)(wsp + kk * 32 + 4);
                float4 hv = hbuf[kk];
                unsigned long long hd0, hd1, hd2, hd3;
                DUP32(hd0, __float_as_uint(hv.x));
                DUP32(hd1, __float_as_uint(hv.y));
                DUP32(hd2, __float_as_uint(hv.z));
                DUP32(hd3, __float_as_uint(hv.w));

                FMA2(acc2[0][0], wA.x, hd0); FMA2(acc2[0][1], wA.x, hd1);
                FMA2(acc2[0][2], wA.x, hd2); FMA2(acc2[0][3], wA.x, hd3);
                FMA2(acc2[1][0], wA.y, hd0); FMA2(acc2[1][1], wA.y, hd1);
                FMA2(acc2[1][2], wA.y, hd2); FMA2(acc2[1][3], wA.y, hd3);
                FMA2(acc2[2][0], wB.x, hd0); FMA2(acc2[2][1], wB.x, hd1);
                FMA2(acc2[2][2], wB.x, hd2); FMA2(acc2[2][3], wB.x, hd3);
                FMA2(acc2[3][0], wB.y, hd0); FMA2(acc2[3][1], wB.y, hd1);
                FMA2(acc2[3][2], wB.y, hd2); FMA2(acc2[3][3], wB.y, hd3);
            }
            #pragma unroll
            for (int i = 0; i < 4; i++) hbuf[i] = hnext[i];
            wsp += 4 * 32;
        }

        // publish partials: part[(w*4+g)*8 + u][36]
        #pragma unroll
        for (int u2 = 0; u2 < 4; u2++) {
            float lo[4], hi[4];
            #pragma unroll
            for (int j = 0; j < 4; j++) {
                unsigned l32, h32;
                UNPK(l32, h32, acc2[u2][j]);
                lo[j] = __uint_as_float(l32);
                hi[j] = __uint_as_float(h32);
            }
            *(float4*)&part[(((w * 4 + g) * 8) + 2 * u2)     * 36 + tb * 4] =
                make_float4(lo[0], lo[1], lo[2], lo[3]);
            *(float4*)&part[(((w * 4 + g) * 8) + 2 * u2 + 1) * 36 + tb * 4] =
                make_float4(hi[0], hi[1], hi[2], hi[3]);
        }
        __syncthreads();

        // ---- epilogue: threads 0..255, thread = (eb, eu) ----
        if (tid < 256) {
            float gate[4];
            #pragma unroll
            for (int g2 = 0; g2 < 4; g2++) {
                float s = 0.f;
                #pragma unroll
                for (int w2 = 0; w2 < 16; w2++)
                    s += part[(((w2 * 4 + g2) * 8) + eu) * 36 + eb];
                gate[g2] = s;
            }
            gate[0] += xpv0;
            gate[1] += xpv1;
            gate[2] += xpv2;
            gate[3] += xpv3;

            float ig = sigmoidf_(gate[0]);
            float fg = sigmoidf_(gate[1]);
            float gv = tanhf_(gate[2]);
            float og = sigmoidf_(gate[3]);

            c_reg = fg * c_reg + ig * gv;
            float h = og * tanhf_(c_reg);

            h_out[(u0 + eu) * B_ + eb] = h;
            out[((size_t)eb * T_ + t) * U_ + u0 + eu] = h;
        }

        // all stores issued; make them block-visible, then barrier
        __syncthreads();

        // prefetch next step's x_proj NOW so its DRAM latency overlaps the wait
        if (t + 1 < T_ && tid < 256) {
            const float* xp = xpb + (size_t)(t + 1) * G4;
            xpv0 = __ldg(xp);
            xpv1 = __ldg(xp + U_);
            xpv2 = __ldg(xp + 2 * U_);
            xpv3 = __ldg(xp + 3 * U_);
        }

        // ---- monotonic-count grid barrier ----
        if (tid == 0) {
            __threadfence();                       // publish h_out (cumulative)
            atomicAdd(&g_count, 1u);               // RED (result unused)
            const unsigned target = (unsigned)NBLK * (unsigned)(t + 1);
            while (*(volatile unsigned*)&g_count < target) {}
            __threadfence();                       // acquire side
        }
        __syncthreads();
    }
}

// ---------------- launch ------------------------------------------------------
extern "C" void kernel_launch(void* const* d_in, const int* in_sizes, int n_in,
                              void* d_out, int out_size) {
    const float* data = (const float*)d_in[0];   // [32,512,512]
    const float* Wx   = (const float*)d_in[1];   // [512,4096]
    const float* Wh   = (const float*)d_in[2];   // [1024,4096]
    const float* bias = (const float*)d_in[3];   // [4096]
    float* out = (float*)d_out;                  // [32,512,1024]

    const int smem_bytes =
        (U_ * 32 + 16 * 4 * 8 * 36) * (int)sizeof(float);   // 128K + 72K = 200K
    cudaFuncSetAttribute(lstm_persistent,
                         cudaFuncAttributeMaxDynamicSharedMemorySize, smem_bytes);

    init_state<<<32, 1024>>>();

    dim3 grid(G4 / 128, (B_ * T_) / 128);        // 32 x 128
    gemm_xproj<<<grid, 256>>>(data, Wx, bias);

    lstm_persistent<<<NBLK, NTHR, smem_bytes>>>(Wh, out);
}

// round 11
// speedup vs baseline: 1.1189x; 1.1189x over previous
#include <cuda_runtime.h>
#include <cuda_bf16.h>
#include <math.h>

#define B_   32
#define T_   512
#define IND  512
#define U_   1024
#define G4   4096   // 4*U
#define NBLK 128
#define NTHR 512
#define MROWS (B_ * T_)   // 16384

// ---------------- scratch (static device globals; no allocs allowed) ----------
__device__ __align__(16) float g_xproj[(size_t)MROWS * G4];      // 256 MB [b*T+t][4U]
__device__ __align__(16) float g_h[2][U_ * B_];                  // ping-pong hT
__device__ unsigned g_count;
__device__ unsigned g_gen;

__device__ __align__(16) __nv_bfloat16 g_dataH[(size_t)MROWS * IND];  // 16 MB
__device__ __align__(16) __nv_bfloat16 g_dataL[(size_t)MROWS * IND];  // 16 MB
__device__ __align__(16) __nv_bfloat16 g_wxTH[(size_t)G4 * IND];      // 4 MB [n][k]
__device__ __align__(16) __nv_bfloat16 g_wxTL[(size_t)G4 * IND];      // 4 MB

// ---------------- init + bf16 hi/lo conversions -------------------------------
__global__ void init_state() {
    int i = blockIdx.x * blockDim.x + threadIdx.x;
    if (i < U_ * B_) g_h[0][i] = 0.f;
}

__global__ void conv_data(const float* __restrict__ A) {
    size_t i = (size_t)blockIdx.x * blockDim.x + threadIdx.x;
    if (i < (size_t)MROWS * IND) {
        float x = A[i];
        __nv_bfloat16 hi = __float2bfloat16(x);
        g_dataH[i] = hi;
        g_dataL[i] = __float2bfloat16(x - __bfloat162float(hi));
    }
}

__global__ void conv_wxT(const float* __restrict__ Wx) {
    size_t i = (size_t)blockIdx.x * blockDim.x + threadIdx.x;   // i = n*512 + k
    if (i < (size_t)G4 * IND) {
        int n = (int)(i >> 9);
        int k = (int)(i & 511);
        float x = Wx[(size_t)k * G4 + n];
        __nv_bfloat16 hi = __float2bfloat16(x);
        g_wxTH[i] = hi;
        g_wxTL[i] = __float2bfloat16(x - __bfloat162float(hi));
    }
}

// ---------------- Kernel 1: bf16x3 mma.sync GEMM: xproj = data @ Wx + b -------
// Block tile 128x128, BK=32, 8 warps (4M x 2N), warp tile 32x64.
// A = data [m][k] hi/lo, B = WxT [n][k] hi/lo. D = AhBh + AhBl + AlBh (fp32 acc).
#define SA 40   // smem row stride in bf16 (80B: conflict-free ldmatrix rotation)

__device__ __forceinline__ unsigned smem_u32(const void* p) {
    unsigned a;
    asm("{ .reg .u64 t; cvta.to.shared.u64 t, %1; cvt.u32.u64 %0, t; }"
        : "=r"(a) : "l"(p));
    return a;
}

#define LDM4(r0, r1, r2, r3, addr) \
    asm volatile("ldmatrix.sync.aligned.m8n8.x4.shared.b16 {%0,%1,%2,%3}, [%4];" \
        : "=r"(r0), "=r"(r1), "=r"(r2), "=r"(r3) : "r"(addr))

#define MMA16816(d, a, b0, b1) \
    asm volatile("mma.sync.aligned.m16n8k16.row.col.f32.bf16.bf16.f32 " \
        "{%0,%1,%2,%3}, {%4,%5,%6,%7}, {%8,%9}, {%0,%1,%2,%3};" \
        : "+f"(d[0]), "+f"(d[1]), "+f"(d[2]), "+f"(d[3]) \
        : "r"(a[0]), "r"(a[1]), "r"(a[2]), "r"(a[3]), "r"(b0), "r"(b1))

__global__ __launch_bounds__(256) void gemm_bf16x3(const float* __restrict__ bias) {
    __shared__ __nv_bfloat16 sAh[128 * SA], sAl[128 * SA];
    __shared__ __nv_bfloat16 sBh[128 * SA], sBl[128 * SA];

    const int tid  = threadIdx.x;
    const int wid  = tid >> 5;
    const int lane = tid & 31;
    const int wm   = wid & 3;          // warp M index (0..3) -> 32 rows
    const int wn   = wid >> 2;         // warp N index (0..1) -> 64 cols
    const int nt   = blockIdx.x * 128;
    const int mt   = blockIdx.y * 128;

    float acc[2][8][4];
    #pragma unroll
    for (int i = 0; i < 2; i++)
        #pragma unroll
        for (int j = 0; j < 8; j++)
            #pragma unroll
            for (int q = 0; q < 4; q++) acc[i][j][q] = 0.f;

    // ldmatrix source addresses (element offsets within tile)
    const unsigned aBase = smem_u32(sAh);
    const unsigned aBaseL = smem_u32(sAl);
    const unsigned bBase = smem_u32(sBh);
    const unsigned bBaseL = smem_u32(sBl);
    const int aRow = wm * 32 + (lane & 15);
    const int aCol = (lane >> 4) * 8;
    const int bRow = wn * 64 + (lane & 7) + ((lane >> 4) << 3);
    const int bCol = ((lane >> 3) & 1) * 8;

    for (int ch = 0; ch < 16; ch++) {
        const int k0 = ch * 32;
        // ---- stage: 512 16B-granules per tile, 2 per thread per tile ----
        #pragma unroll
        for (int i = 0; i < 2; i++) {
            int gidx = tid + i * 256;       // 0..511
            int row  = gidx >> 2;
            int kq   = gidx & 3;
            size_t ga = (size_t)(mt + row) * IND + k0 + kq * 8;
            size_t gb = (size_t)(nt + row) * IND + k0 + kq * 8;
            *(uint4*)&sAh[row * SA + kq * 8] = *(const uint4*)(g_dataH + ga);
            *(uint4*)&sAl[row * SA + kq * 8] = *(const uint4*)(g_dataL + ga);
            *(uint4*)&sBh[row * SA + kq * 8] = *(const uint4*)(g_wxTH + gb);
            *(uint4*)&sBl[row * SA + kq * 8] = *(const uint4*)(g_wxTL + gb);
        }
        __syncthreads();

        #pragma unroll
        for (int ks = 0; ks < 2; ks++) {
            unsigned ah[2][4], al[2][4];
            #pragma unroll
            for (int mi = 0; mi < 2; mi++) {
                unsigned off = (unsigned)(((aRow + mi * 16) * SA + ks * 16 + aCol) * 2);
                LDM4(ah[mi][0], ah[mi][1], ah[mi][2], ah[mi][3], aBase + off);
                LDM4(al[mi][0], al[mi][1], al[mi][2], al[mi][3], aBaseL + off);
            }
            unsigned bh[4][4], bl[4][4];
            #pragma unroll
            for (int n4 = 0; n4 < 4; n4++) {
                unsigned off = (unsigned)(((bRow + n4 * 16) * SA + ks * 16 + bCol) * 2);
                LDM4(bh[n4][0], bh[n4][1], bh[n4][2], bh[n4][3], bBase + off);
                LDM4(bl[n4][0], bl[n4][1], bl[n4][2], bl[n4][3], bBaseL + off);
            }
            #pragma unroll
            for (int mi = 0; mi < 2; mi++)
                #pragma unroll
                for (int ni = 0; ni < 8; ni++) {
                    unsigned bh0 = bh[ni >> 1][(ni & 1) * 2];
                    unsigned bh1 = bh[ni >> 1][(ni & 1) * 2 + 1];
                    unsigned bl0 = bl[ni >> 1][(ni & 1) * 2];
                    unsigned bl1 = bl[ni >> 1][(ni & 1) * 2 + 1];
                    MMA16816(acc[mi][ni], ah[mi], bh0, bh1);
                    MMA16816(acc[mi][ni], ah[mi], bl0, bl1);
                    MMA16816(acc[mi][ni], al[mi], bh0, bh1);
                }
        }
        __syncthreads();
    }

    // ---- epilogue: acc layout d0,d1=row lane>>2 cols +(lane&3)*2; d2,d3=row+8
    const int row0 = mt + wm * 32 + (lane >> 2);
    const int col0 = nt + wn * 64 + (lane & 3) * 2;
    #pragma unroll
    for (int mi = 0; mi < 2; mi++)
        #pragma unroll
        for (int ni = 0; ni < 8; ni++) {
            int c = col0 + ni * 8;
            float bv0 = __ldg(bias + c);
            float bv1 = __ldg(bias + c + 1);
            int r = row0 + mi * 16;
            *(float2*)(g_xproj + (size_t)r * G4 + c) =
                make_float2(acc[mi][ni][0] + bv0, acc[mi][ni][1] + bv1);
            *(float2*)(g_xproj + (size_t)(r + 8) * G4 + c) =
                make_float2(acc[mi][ni][2] + bv0, acc[mi][ni][3] + bv1);
        }
}

// ---------------- Kernel 2: persistent LSTM recurrence (R6, 6713us-proven) ----
__device__ __forceinline__ float sigmoidf_(float x) {
    return 1.f / (1.f + __expf(-x));
}
__device__ __forceinline__ float tanhf_(float x) {
    return 2.f / (1.f + __expf(-2.f * x)) - 1.f;
}

#define FMA2(acc, a, b) \
    asm("fma.rn.f32x2 %0, %1, %2, %0;" : "+l"(acc) : "l"(a), "l"(b))
#define DUP32(dst, src) \
    asm("mov.b64 %0, {%1, %1};" : "=l"(dst) : "r"(src))
#define UNPK(lo, hi, v) \
    asm("mov.b64 {%0, %1}, %2;" : "=r"(lo), "=r"(hi) : "l"(v))

extern __shared__ float smem_dyn[];

__global__ __launch_bounds__(NTHR) void lstm_persistent(
    const float* __restrict__ Wh,   // [1024][4096]
    float* __restrict__ out)        // [32][512][1024]
{
    float* ws   = smem_dyn;                  // [1024][32]  128 KB
    float* part = smem_dyn + U_ * 32;        // [16*4*8][36] 72 KB

    const int tid  = threadIdx.x;
    const int w    = tid >> 5;               // 0..15
    const int lane = tid & 31;
    const int g    = lane & 3;
    const int tb   = lane >> 2;
    const int u0   = blockIdx.x * 8;

    for (int idx = tid; idx < U_ * 8; idx += NTHR) {
        int k  = idx >> 3;
        int r  = idx & 7;
        int g2 = r >> 1;
        int hf = r & 1;
        float4 v = *(const float4*)(Wh + (size_t)k * G4 + g2 * U_ + u0 + hf * 4);
        *(float4*)&ws[k * 32 + g2 * 8 + hf * 4] = v;
    }

    const int eb = (tid >> 3) & 31;
    const int eu = tid & 7;
    float c_reg = 0.f;

    unsigned my_gen = *(volatile unsigned*)&g_gen;
    __syncthreads();

    const float* wsp_base = ws + (size_t)(w * 64) * 32 + g * 8;

    for (int t = 0; t < T_; t++) {
        const float* __restrict__ h_in = g_h[t & 1];
        float* __restrict__ h_out      = g_h[(t + 1) & 1];

        float xpv0, xpv1, xpv2, xpv3;
        if (tid < 256) {
            const float* xp = g_xproj + ((size_t)eb * T_ + t) * G4 + u0 + eu;
            xpv0 = __ldg(xp);
            xpv1 = __ldg(xp + U_);
            xpv2 = __ldg(xp + 2 * U_);
            xpv3 = __ldg(xp + 3 * U_);
        }

        unsigned long long acc2[4][4];
        #pragma unroll
        for (int i = 0; i < 4; i++)
            #pragma unroll
            for (int j = 0; j < 4; j++) acc2[i][j] = 0ULL;

        const float* wsp = wsp_base;
        const float4* hp = (const float4*)(h_in + (w * 64) * B_) + tb;

        float4 hbuf[4];
        #pragma unroll
        for (int i = 0; i < 4; i++) hbuf[i] = __ldcg(hp + i * 8);

        #pragma unroll 2
        for (int kg = 0; kg < 16; kg++) {
            float4 hnext[4];
            if (kg < 15) {
                #pragma unroll
                for (int i = 0; i < 4; i++)
                    hnext[i] = __ldcg(hp + (kg + 1) * 32 + i * 8);
            }
            #pragma unroll
            for (int kk = 0; kk < 4; kk++) {
                ulonglong2 wA = *(const ulonglong2*)(wsp + kk * 32);
                ulonglong2 wB = *(const ulonglong2*)(wsp + kk * 32 + 4);
                float4 hv = hbuf[kk];
                unsigned long long hd0, hd1, hd2, hd3;
                DUP32(hd0, __float_as_uint(hv.x));
                DUP32(hd1, __float_as_uint(hv.y));
                DUP32(hd2, __float_as_uint(hv.z));
                DUP32(hd3, __float_as_uint(hv.w));

                FMA2(acc2[0][0], wA.x, hd0); FMA2(acc2[0][1], wA.x, hd1);
                FMA2(acc2[0][2], wA.x, hd2); FMA2(acc2[0][3], wA.x, hd3);
                FMA2(acc2[1][0], wA.y, hd0); FMA2(acc2[1][1], wA.y, hd1);
                FMA2(acc2[1][2], wA.y, hd2); FMA2(acc2[1][3], wA.y, hd3);
                FMA2(acc2[2][0], wB.x, hd0); FMA2(acc2[2][1], wB.x, hd1);
                FMA2(acc2[2][2], wB.x, hd2); FMA2(acc2[2][3], wB.x, hd3);
                FMA2(acc2[3][0], wB.y, hd0); FMA2(acc2[3][1], wB.y, hd1);
                FMA2(acc2[3][2], wB.y, hd2); FMA2(acc2[3][3], wB.y, hd3);
            }
            #pragma unroll
            for (int i = 0; i < 4; i++) hbuf[i] = hnext[i];
            wsp += 4 * 32;
        }

        #pragma unroll
        for (int u2 = 0; u2 < 4; u2++) {
            float lo[4], hi[4];
            #pragma unroll
            for (int j = 0; j < 4; j++) {
                unsigned l32, h32;
                UNPK(l32, h32, acc2[u2][j]);
                lo[j] = __uint_as_float(l32);
                hi[j] = __uint_as_float(h32);
            }
            *(float4*)&part[(((w * 4 + g) * 8) + 2 * u2)     * 36 + tb * 4] =
                make_float4(lo[0], lo[1], lo[2], lo[3]);
            *(float4*)&part[(((w * 4 + g) * 8) + 2 * u2 + 1) * 36 + tb * 4] =
                make_float4(hi[0], hi[1], hi[2], hi[3]);
        }
        __syncthreads();

        if (tid < 256) {
            float gate[4];
            #pragma unroll
            for (int g2 = 0; g2 < 4; g2++) {
                float s = 0.f;
                #pragma unroll
                for (int w2 = 0; w2 < 16; w2++)
                    s += part[(((w2 * 4 + g2) * 8) + eu) * 36 + eb];
                gate[g2] = s;
            }
            gate[0] += xpv0;
            gate[1] += xpv1;
            gate[2] += xpv2;
            gate[3] += xpv3;

            float ig = sigmoidf_(gate[0]);
            float fg = sigmoidf_(gate[1]);
            float gv = tanhf_(gate[2]);
            float og = sigmoidf_(gate[3]);

            c_reg = fg * c_reg + ig * gv;
            float h = og * tanhf_(c_reg);

            h_out[(u0 + eu) * B_ + eb] = h;
            out[((size_t)eb * T_ + t) * U_ + u0 + eu] = h;
        }

        __syncthreads();
        if (tid == 0) {
            __threadfence();
            if (atomicAdd(&g_count, 1u) == NBLK - 1) {
                atomicExch(&g_count, 0u);
                __threadfence();
                atomicAdd(&g_gen, 1u);
            } else {
                while (*(volatile unsigned*)&g_gen == my_gen) {}
            }
            my_gen++;
        }
        __syncthreads();
    }
}

// ---------------- launch ------------------------------------------------------
extern "C" void kernel_launch(void* const* d_in, const int* in_sizes, int n_in,
                              void* d_out, int out_size) {
    const float* data = (const float*)d_in[0];   // [32,512,512]
    const float* Wx   = (const float*)d_in[1];   // [512,4096]
    const float* Wh   = (const float*)d_in[2];   // [1024,4096]
    const float* bias = (const float*)d_in[3];   // [4096]
    float* out = (float*)d_out;                  // [32,512,1024]

    const int smem_rec =
        (U_ * 32 + 16 * 4 * 8 * 36) * (int)sizeof(float);   // 200 KB
    cudaFuncSetAttribute(lstm_persistent,
                         cudaFuncAttributeMaxDynamicSharedMemorySize, smem_rec);

    init_state<<<32, 1024>>>();
    conv_data<<<(MROWS * IND) / 256, 256>>>(data);
    conv_wxT<<<(G4 * IND) / 256, 256>>>(Wx);

    dim3 ggrid(G4 / 128, MROWS / 128);           // (32, 128)
    gemm_bf16x3<<<ggrid, 256>>>(bias);

    lstm_persistent<<<NBLK, NTHR, smem_rec>>>(Wh, out);
}